// round 4
// baseline (speedup 1.0000x reference)
#include <cuda_runtime.h>
#include <cstdint>

// Problem constants (fixed by reference: POOL=100, N_TASKS=5 -> F_END=20)
#define KEY_D   768
#define EMB_D   768
#define P_FEAT  9216      // EMB_D * HEADS
#define E_P_LEN 8
#define FEND    20
#define TOPKN   10
#define EPSV    1e-12f

// Kernel-1 tiling
#define QPB 8             // queries per block
#define K1_THREADS 640    // 20 warps, warp w <-> key w

// Kernel-2 tiling
#define K2_THREADS 128    // 4 warps; each warp owns 64 d-cols (2 per lane)
#define DBLK 256          // d-columns per block (4 warps x 64)
#define QT   128          // queries per block

// Prepacked gate scratch: [BQ][FEND] of float2 {g,g}; supports BQ up to 4096
__device__ float2 g_gate2[4096 * FEND];

// ---------------------------------------------------------------------------
// packed f32x2 helpers
// ---------------------------------------------------------------------------
__device__ __forceinline__ void fma2(unsigned long long& d,
                                     unsigned long long a,
                                     unsigned long long b) {
    asm("fma.rn.f32x2 %0, %1, %2, %0;" : "+l"(d) : "l"(a), "l"(b));
}

// ---------------------------------------------------------------------------
// Kernel 1: 8 queries per block, 20 warps (one per key).
// Each warp holds its A/K rows in registers and loops the 8 staged query rows.
// Thread t<8 then does top-10 + softmax and writes PRE-DUPLICATED gate pairs.
// ---------------------------------------------------------------------------
__global__ __launch_bounds__(K1_THREADS)
void scores_gate_kernel(const float* __restrict__ x,
                        const float* __restrict__ K,
                        const float* __restrict__ A,
                        int BQ) {
    __shared__ float x_s[QPB][KEY_D];   // 24 KB
    __shared__ float sc[QPB][FEND];

    const int q0  = blockIdx.x * QPB;
    const int tid = threadIdx.x;
    const int w   = tid >> 5;           // key index (0..19)
    const int lane = tid & 31;

    // stage QPB query rows
    {
        const float4* src = (const float4*)(x + (size_t)q0 * KEY_D);
        for (int i = tid; i < QPB * KEY_D / 4; i += K1_THREADS)
            ((float4*)&x_s[0][0])[i] = src[i];
    }
    __syncthreads();

    // this warp's A/K rows in registers
    float4 a6[6], k6[6];
    {
        const float4* Ar = (const float4*)(A + (size_t)w * KEY_D);
        const float4* Kr = (const float4*)(K + (size_t)w * KEY_D);
#pragma unroll
        for (int i = 0; i < 6; ++i) {
            a6[i] = Ar[lane + 32 * i];
            k6[i] = Kr[lane + 32 * i];
        }
    }
    float nk = 0.f;
#pragma unroll
    for (int i = 0; i < 6; ++i) {
        nk = fmaf(k6[i].x, k6[i].x, nk);
        nk = fmaf(k6[i].y, k6[i].y, nk);
        nk = fmaf(k6[i].z, k6[i].z, nk);
        nk = fmaf(k6[i].w, k6[i].w, nk);
    }
#pragma unroll
    for (int off = 16; off; off >>= 1)
        nk += __shfl_xor_sync(0xFFFFFFFFu, nk, off);
    const float nKc = fmaxf(sqrtf(nk), EPSV);

#pragma unroll
    for (int q = 0; q < QPB; ++q) {
        const float4* xs4 = (const float4*)x_s[q];
        float dot = 0.f, na = 0.f;
#pragma unroll
        for (int i = 0; i < 6; ++i) {
            float4 xa = xs4[lane + 32 * i];
            float t;
            t = xa.x * a6[i].x; dot = fmaf(t, k6[i].x, dot); na = fmaf(t, t, na);
            t = xa.y * a6[i].y; dot = fmaf(t, k6[i].y, dot); na = fmaf(t, t, na);
            t = xa.z * a6[i].z; dot = fmaf(t, k6[i].z, dot); na = fmaf(t, t, na);
            t = xa.w * a6[i].w; dot = fmaf(t, k6[i].w, dot); na = fmaf(t, t, na);
        }
#pragma unroll
        for (int off = 16; off; off >>= 1) {
            dot += __shfl_xor_sync(0xFFFFFFFFu, dot, off);
            na  += __shfl_xor_sync(0xFFFFFFFFu, na,  off);
        }
        if (lane == 0)
            sc[q][w] = dot / (fmaxf(sqrtf(na), EPSV) * nKc);
    }
    __syncthreads();

    if (tid < QPB && q0 + tid < BQ) {
        float s[FEND];
#pragma unroll
        for (int k = 0; k < FEND; ++k) s[k] = sc[tid][k];
        float tv[TOPKN]; int ti[TOPKN];
#pragma unroll
        for (int j = 0; j < TOPKN; ++j) {
            int bi = 0; float bv = -__int_as_float(0x7F800000); // -inf
#pragma unroll
            for (int k = 0; k < FEND; ++k)
                if (s[k] > bv) { bv = s[k]; bi = k; }
            tv[j] = bv; ti[j] = bi;
            s[bi] = -__int_as_float(0x7F800000);
        }
        float m = tv[0], sum = 0.f;
        float e[TOPKN];
#pragma unroll
        for (int j = 0; j < TOPKN; ++j) { e[j] = __expf(tv[j] - m); sum += e[j]; }
        float inv = 1.f / sum;
        float g[FEND];
#pragma unroll
        for (int k = 0; k < FEND; ++k) g[k] = 0.f;
#pragma unroll
        for (int j = 0; j < TOPKN; ++j) g[ti[j]] = e[j] * inv;
        float2* gr = g_gate2 + (size_t)(q0 + tid) * FEND;
#pragma unroll
        for (int k = 0; k < FEND; ++k) gr[k] = make_float2(g[k], g[k]);
    }
}

// ---------------------------------------------------------------------------
// Kernel 2 (v3): p register-resident, queries stream past it.
// Grid: (P_FEAT/DBLK, 8, BQ/QT). Block: 128 threads (4 warps).
// Each lane owns 2 consecutive d-columns (one f32x2) of plane l and keeps the
// 20 p pairs in registers. Gates (pre-duplicated pairs) are staged in smem and
// read as warp-uniform LDS.128 broadcasts. 4 queries in flight per thread.
// ---------------------------------------------------------------------------
__global__ __launch_bounds__(K2_THREADS)
void expand_kernel(const float* __restrict__ p,
                   float* __restrict__ out,
                   int BQ) {
    __shared__ float gs[QT * FEND * 2];   // 20 KB: per query, 20 float2 pairs

    const int tid  = threadIdx.x;
    const int l    = blockIdx.y;
    const int q0   = blockIdx.z * QT;
    const int d0   = blockIdx.x * DBLK + (tid >> 5) * 64 + (tid & 31) * 2;

    // stage packed gates for this query tile (coalesced float4 copy)
    {
        const float4* src =
            (const float4*)((const float*)g_gate2 + (size_t)q0 * FEND * 2);
        for (int i = tid; i < QT * FEND * 2 / 4; i += K2_THREADS)
            ((float4*)gs)[i] = src[i];
    }

    // p pairs for this lane's 2 d-columns, all 20 k, into registers
    unsigned long long pr[FEND];
#pragma unroll
    for (int k = 0; k < FEND; ++k)
        pr[k] = *(const unsigned long long*)
                    (p + ((size_t)k * E_P_LEN + l) * P_FEAT + d0);

    __syncthreads();

    const size_t base = (l < 4) ? 0 : (size_t)BQ * 4;
    const int lrow = l & 3;

    for (int qc = 0; qc < QT; qc += 4) {
        const ulonglong2* g0 = (const ulonglong2*)(gs + (qc + 0) * FEND * 2);
        const ulonglong2* g1 = (const ulonglong2*)(gs + (qc + 1) * FEND * 2);
        const ulonglong2* g2 = (const ulonglong2*)(gs + (qc + 2) * FEND * 2);
        const ulonglong2* g3 = (const ulonglong2*)(gs + (qc + 3) * FEND * 2);

        unsigned long long a0 = 0ull, a1 = 0ull, a2 = 0ull, a3 = 0ull;
#pragma unroll
        for (int j = 0; j < FEND / 2; ++j) {   // 10 iters, 2 k per iter
            ulonglong2 v0 = g0[j];
            ulonglong2 v1 = g1[j];
            ulonglong2 v2 = g2[j];
            ulonglong2 v3 = g3[j];
            fma2(a0, v0.x, pr[2 * j]); fma2(a0, v0.y, pr[2 * j + 1]);
            fma2(a1, v1.x, pr[2 * j]); fma2(a1, v1.y, pr[2 * j + 1]);
            fma2(a2, v2.x, pr[2 * j]); fma2(a2, v2.y, pr[2 * j + 1]);
            fma2(a3, v3.x, pr[2 * j]); fma2(a3, v3.y, pr[2 * j + 1]);
        }

        const int q = q0 + qc;
        if (q + 0 < BQ)
            *(unsigned long long*)(out + (base + (size_t)(q + 0) * 4 + lrow) * P_FEAT + d0) = a0;
        if (q + 1 < BQ)
            *(unsigned long long*)(out + (base + (size_t)(q + 1) * 4 + lrow) * P_FEAT + d0) = a1;
        if (q + 2 < BQ)
            *(unsigned long long*)(out + (base + (size_t)(q + 2) * 4 + lrow) * P_FEAT + d0) = a2;
        if (q + 3 < BQ)
            *(unsigned long long*)(out + (base + (size_t)(q + 3) * 4 + lrow) * P_FEAT + d0) = a3;
    }
}

// ---------------------------------------------------------------------------
// Launch
// ---------------------------------------------------------------------------
extern "C" void kernel_launch(void* const* d_in, const int* in_sizes, int n_in,
                              void* d_out, int out_size) {
    // Inputs (metadata order): x_querry, l, x_block, K, A, p.
    int iK, iA, ip;
    if (n_in >= 6 && in_sizes[1] == 1) { iK = 3; iA = 4; ip = 5; }
    else                               { iK = 2; iA = 3; ip = 4; }

    const float* x = (const float*)d_in[0];
    const float* K = (const float*)d_in[iK];
    const float* A = (const float*)d_in[iA];
    const float* p = (const float*)d_in[ip];
    float*     out = (float*)d_out;

    const int BQ = in_sizes[0] / KEY_D;   // 1024 for (4, 256)

    scores_gate_kernel<<<(BQ + QPB - 1) / QPB, K1_THREADS>>>(x, K, A, BQ);

    dim3 grid(P_FEAT / DBLK, E_P_LEN, (BQ + QT - 1) / QT);
    expand_kernel<<<grid, K2_THREADS>>>(p, out, BQ);
}

// round 5
// speedup vs baseline: 1.3227x; 1.3227x over previous
#include <cuda_runtime.h>
#include <cstdint>

// Problem constants (fixed by reference: POOL=100, N_TASKS=5 -> F_END=20)
#define KEY_D   768
#define EMB_D   768
#define P_FEAT  9216      // EMB_D * HEADS
#define E_P_LEN 8
#define FEND    20
#define TOPKN   10
#define EPSV    1e-12f

// Kernel-1 tiling
#define QPB 8             // queries per block
#define K1_THREADS 640    // 20 warps, warp w <-> key w

// Kernel-2 tiling
#define DC  128           // d-chunk per block
#define QB2 128           // queries per block (16 per warp)
#define K2_THREADS 256    // 8 warps

// Dense gate scratch: [BQ][FEND], supports BQ up to 4096
__device__ float g_gate[4096 * FEND];

// ---------------------------------------------------------------------------
// packed f32x2 helpers
// ---------------------------------------------------------------------------
__device__ __forceinline__ void fma2(unsigned long long& d,
                                     unsigned long long a,
                                     unsigned long long b) {
    asm("fma.rn.f32x2 %0, %1, %2, %0;" : "+l"(d) : "l"(a), "l"(b));
}
__device__ __forceinline__ unsigned long long pack2(float x) {
    unsigned long long r;
    asm("mov.b64 %0, {%1, %1};" : "=l"(r) : "f"(x));
    return r;
}
__device__ __forceinline__ float2 unpack2(unsigned long long v) {
    float2 r;
    asm("mov.b64 {%0, %1}, %2;" : "=f"(r.x), "=f"(r.y) : "l"(v));
    return r;
}

// ---------------------------------------------------------------------------
// Kernel 1: 8 queries per block, 20 warps (one per key).
// Each warp holds its A/K rows in registers and loops the 8 staged query rows.
// Thread t<8 then does top-10 + softmax -> dense gate row.
// ---------------------------------------------------------------------------
__global__ __launch_bounds__(K1_THREADS)
void scores_gate_kernel(const float* __restrict__ x,
                        const float* __restrict__ K,
                        const float* __restrict__ A,
                        int BQ) {
    __shared__ float x_s[QPB][KEY_D];   // 24 KB
    __shared__ float sc[QPB][FEND];

    const int q0  = blockIdx.x * QPB;
    const int tid = threadIdx.x;
    const int w   = tid >> 5;           // key index (0..19)
    const int lane = tid & 31;

    // stage QPB query rows
    {
        const float4* src = (const float4*)(x + (size_t)q0 * KEY_D);
        for (int i = tid; i < QPB * KEY_D / 4; i += K1_THREADS)
            ((float4*)&x_s[0][0])[i] = src[i];
    }
    __syncthreads();

    // this warp's A/K rows in registers
    float4 a6[6], k6[6];
    {
        const float4* Ar = (const float4*)(A + (size_t)w * KEY_D);
        const float4* Kr = (const float4*)(K + (size_t)w * KEY_D);
#pragma unroll
        for (int i = 0; i < 6; ++i) {
            a6[i] = Ar[lane + 32 * i];
            k6[i] = Kr[lane + 32 * i];
        }
    }
    float nk = 0.f;
#pragma unroll
    for (int i = 0; i < 6; ++i) {
        nk = fmaf(k6[i].x, k6[i].x, nk);
        nk = fmaf(k6[i].y, k6[i].y, nk);
        nk = fmaf(k6[i].z, k6[i].z, nk);
        nk = fmaf(k6[i].w, k6[i].w, nk);
    }
#pragma unroll
    for (int off = 16; off; off >>= 1)
        nk += __shfl_xor_sync(0xFFFFFFFFu, nk, off);
    const float nKc = fmaxf(sqrtf(nk), EPSV);

#pragma unroll
    for (int q = 0; q < QPB; ++q) {
        const float4* xs4 = (const float4*)x_s[q];
        float dot = 0.f, na = 0.f;
#pragma unroll
        for (int i = 0; i < 6; ++i) {
            float4 xa = xs4[lane + 32 * i];
            float t;
            t = xa.x * a6[i].x; dot = fmaf(t, k6[i].x, dot); na = fmaf(t, t, na);
            t = xa.y * a6[i].y; dot = fmaf(t, k6[i].y, dot); na = fmaf(t, t, na);
            t = xa.z * a6[i].z; dot = fmaf(t, k6[i].z, dot); na = fmaf(t, t, na);
            t = xa.w * a6[i].w; dot = fmaf(t, k6[i].w, dot); na = fmaf(t, t, na);
        }
#pragma unroll
        for (int off = 16; off; off >>= 1) {
            dot += __shfl_xor_sync(0xFFFFFFFFu, dot, off);
            na  += __shfl_xor_sync(0xFFFFFFFFu, na,  off);
        }
        if (lane == 0)
            sc[q][w] = dot / (fmaxf(sqrtf(na), EPSV) * nKc);
    }
    __syncthreads();

    if (tid < QPB && q0 + tid < BQ) {
        float s[FEND];
#pragma unroll
        for (int k = 0; k < FEND; ++k) s[k] = sc[tid][k];
        float tv[TOPKN]; int ti[TOPKN];
#pragma unroll
        for (int j = 0; j < TOPKN; ++j) {
            int bi = 0; float bv = -__int_as_float(0x7F800000); // -inf
#pragma unroll
            for (int k = 0; k < FEND; ++k)
                if (s[k] > bv) { bv = s[k]; bi = k; }
            tv[j] = bv; ti[j] = bi;
            s[bi] = -__int_as_float(0x7F800000);
        }
        float m = tv[0], sum = 0.f;
        float e[TOPKN];
#pragma unroll
        for (int j = 0; j < TOPKN; ++j) { e[j] = __expf(tv[j] - m); sum += e[j]; }
        float inv = 1.f / sum;
        float* gr = g_gate + (size_t)(q0 + tid) * FEND;
#pragma unroll
        for (int k = 0; k < FEND; ++k) gr[k] = 0.f;
#pragma unroll
        for (int j = 0; j < TOPKN; ++j) gr[ti[j]] = e[j] * inv;
    }
}

// ---------------------------------------------------------------------------
// Kernel 2 (v4): dense K=20 mini-GEMM, 16 queries per warp.
// Grid: (P_FEAT/DC, 8, BQ/QB2). Block: 256 threads (8 warps).
// Block tile: 128 queries x 128 d. Warp w owns queries [w*16, w*16+16);
// lane owns 4 d-cols (one float4 of p). acc[8][4]: 8 query-pairs x 4 d,
// queries packed in the 2 f32x2 lanes. Per warp-k: 1 p LDS.128 (lane-
// distinct) + 4 gate LDS.128 (uniform broadcast) + 4 pack2 + 32 fma2.
// ---------------------------------------------------------------------------
__global__ __launch_bounds__(K2_THREADS, 2)
void expand_kernel(const float* __restrict__ p,
                   float* __restrict__ out,
                   int BQ) {
    __shared__ float ps_s[FEND * DC];    // [k][128]  10 KB
    __shared__ float gt_s[FEND * QB2];   // [k][128]  10 KB

    const int d0  = blockIdx.x * DC;
    const int l   = blockIdx.y;
    const int q0  = blockIdx.z * QB2;
    const int tid = threadIdx.x;

    // stage p tile: rows k, columns d0..d0+127 of plane (k, l)
    for (int i = tid; i < FEND * (DC / 4); i += K2_THREADS) {
        int k = i / (DC / 4);
        int c = i % (DC / 4);
        ((float4*)ps_s)[i] =
            *(const float4*)(p + ((size_t)(k * E_P_LEN + l)) * P_FEAT + d0 + c * 4);
    }
    // stage gate tile, transposed to [k][q]
    for (int i = tid; i < FEND * QB2; i += K2_THREADS) {
        int k = i / QB2, q = i % QB2;
        int qq = q0 + q;
        gt_s[k * QB2 + q] = (qq < BQ) ? g_gate[(size_t)qq * FEND + k] : 0.f;
    }
    __syncthreads();

    const int lane = tid & 31;    // d position within chunk (x4)
    const int w    = tid >> 5;    // query group of 16

    unsigned long long acc[8][4];
#pragma unroll
    for (int a = 0; a < 8; ++a)
#pragma unroll
        for (int b = 0; b < 4; ++b) acc[a][b] = 0ull;

#pragma unroll 4
    for (int k = 0; k < FEND; ++k) {
        float4 pv = ((const float4*)ps_s)[k * (DC / 4) + lane];
        unsigned long long pp[4];
        pp[0] = pack2(pv.x);
        pp[1] = pack2(pv.y);
        pp[2] = pack2(pv.z);
        pp[3] = pack2(pv.w);
        // 16 gates = 8 query-pairs, uniform per warp
        const ulonglong2* gp = (const ulonglong2*)(gt_s + k * QB2 + w * 16);
        ulonglong2 ga = gp[0];   // pairs 0,1
        ulonglong2 gb = gp[1];   // pairs 2,3
        ulonglong2 gc = gp[2];   // pairs 4,5
        ulonglong2 gd = gp[3];   // pairs 6,7
        unsigned long long gv[8] = { ga.x, ga.y, gb.x, gb.y,
                                     gc.x, gc.y, gd.x, gd.y };
#pragma unroll
        for (int qp = 0; qp < 8; ++qp) {
            fma2(acc[qp][0], gv[qp], pp[0]);
            fma2(acc[qp][1], gv[qp], pp[1]);
            fma2(acc[qp][2], gv[qp], pp[2]);
            fma2(acc[qp][3], gv[qp], pp[3]);
        }
    }

    // writeout: Ek = rows [0, BQ*4), Ev = rows [BQ*4, BQ*8)
    const size_t base = (l < 4) ? 0 : (size_t)BQ * 4;
    const int lrow = l & 3;
    const int dcol = d0 + lane * 4;
#pragma unroll
    for (int qp = 0; qp < 8; ++qp) {
        float2 u0 = unpack2(acc[qp][0]);
        float2 u1 = unpack2(acc[qp][1]);
        float2 u2 = unpack2(acc[qp][2]);
        float2 u3 = unpack2(acc[qp][3]);
        int q = q0 + w * 16 + qp * 2;
        float4 o0 = make_float4(u0.x, u1.x, u2.x, u3.x);
        float4 o1 = make_float4(u0.y, u1.y, u2.y, u3.y);
        if (q < BQ)
            *(float4*)(out + (base + (size_t)q * 4 + lrow) * P_FEAT + dcol) = o0;
        if (q + 1 < BQ)
            *(float4*)(out + (base + (size_t)(q + 1) * 4 + lrow) * P_FEAT + dcol) = o1;
    }
}

// ---------------------------------------------------------------------------
// Launch
// ---------------------------------------------------------------------------
extern "C" void kernel_launch(void* const* d_in, const int* in_sizes, int n_in,
                              void* d_out, int out_size) {
    // Inputs (metadata order): x_querry, l, x_block, K, A, p.
    int iK, iA, ip;
    if (n_in >= 6 && in_sizes[1] == 1) { iK = 3; iA = 4; ip = 5; }
    else                               { iK = 2; iA = 3; ip = 4; }

    const float* x = (const float*)d_in[0];
    const float* K = (const float*)d_in[iK];
    const float* A = (const float*)d_in[iA];
    const float* p = (const float*)d_in[ip];
    float*     out = (float*)d_out;

    const int BQ = in_sizes[0] / KEY_D;   // 1024 for (4, 256)

    scores_gate_kernel<<<(BQ + QPB - 1) / QPB, K1_THREADS>>>(x, K, A, BQ);

    dim3 grid(P_FEAT / DC, E_P_LEN, (BQ + QB2 - 1) / QB2);
    expand_kernel<<<grid, K2_THREADS>>>(p, out, BQ);
}

// round 6
// speedup vs baseline: 1.4976x; 1.1322x over previous
#include <cuda_runtime.h>
#include <cstdint>

// Problem constants (fixed by reference: POOL=100, N_TASKS=5 -> F_END=20)
#define KEY_D   768
#define EMB_D   768
#define P_FEAT  9216      // EMB_D * HEADS
#define E_P_LEN 8
#define FEND    20
#define TOPKN   10
#define EPSV    1e-12f

// Kernel-1 tiling
#define QPB 8             // queries per block
#define K1_THREADS 640    // 20 warps, warp w <-> key w

// Kernel-2 tiling
#define DC  128           // d-chunk per block
#define QB2 128           // queries per block (16 per warp)
#define K2_THREADS 256    // 8 warps

// Transposed dense gate scratch: [FEND][QMAX] (k-major, coalesced consumer)
#define QMAX 4096
__device__ float g_gateT[FEND * QMAX];

// ---------------------------------------------------------------------------
// packed f32x2 helpers
// ---------------------------------------------------------------------------
__device__ __forceinline__ void fma2(unsigned long long& d,
                                     unsigned long long a,
                                     unsigned long long b) {
    asm("fma.rn.f32x2 %0, %1, %2, %0;" : "+l"(d) : "l"(a), "l"(b));
}
__device__ __forceinline__ unsigned long long pack2(float x) {
    unsigned long long r;
    asm("mov.b64 %0, {%1, %1};" : "=l"(r) : "f"(x));
    return r;
}
__device__ __forceinline__ float2 unpack2(unsigned long long v) {
    float2 r;
    asm("mov.b64 {%0, %1}, %2;" : "=f"(r.x), "=f"(r.y) : "l"(v));
    return r;
}

// ---------------------------------------------------------------------------
// Kernel 1: 8 queries per block, 20 warps (one per key).
// Each warp holds its A/K rows in registers and loops the 8 staged query rows.
// Thread t<8 then does top-10 + softmax -> TRANSPOSED dense gate rows.
// ---------------------------------------------------------------------------
__global__ __launch_bounds__(K1_THREADS)
void scores_gate_kernel(const float* __restrict__ x,
                        const float* __restrict__ K,
                        const float* __restrict__ A,
                        int BQ) {
    __shared__ float x_s[QPB][KEY_D];   // 24 KB
    __shared__ float sc[QPB][FEND];

    const int q0  = blockIdx.x * QPB;
    const int tid = threadIdx.x;
    const int w   = tid >> 5;           // key index (0..19)
    const int lane = tid & 31;

    // stage QPB query rows
    {
        const float4* src = (const float4*)(x + (size_t)q0 * KEY_D);
        for (int i = tid; i < QPB * KEY_D / 4; i += K1_THREADS)
            ((float4*)&x_s[0][0])[i] = src[i];
    }
    __syncthreads();

    // this warp's A/K rows in registers
    float4 a6[6], k6[6];
    {
        const float4* Ar = (const float4*)(A + (size_t)w * KEY_D);
        const float4* Kr = (const float4*)(K + (size_t)w * KEY_D);
#pragma unroll
        for (int i = 0; i < 6; ++i) {
            a6[i] = Ar[lane + 32 * i];
            k6[i] = Kr[lane + 32 * i];
        }
    }
    float nk = 0.f;
#pragma unroll
    for (int i = 0; i < 6; ++i) {
        nk = fmaf(k6[i].x, k6[i].x, nk);
        nk = fmaf(k6[i].y, k6[i].y, nk);
        nk = fmaf(k6[i].z, k6[i].z, nk);
        nk = fmaf(k6[i].w, k6[i].w, nk);
    }
#pragma unroll
    for (int off = 16; off; off >>= 1)
        nk += __shfl_xor_sync(0xFFFFFFFFu, nk, off);
    const float nKc = fmaxf(sqrtf(nk), EPSV);

#pragma unroll
    for (int q = 0; q < QPB; ++q) {
        const float4* xs4 = (const float4*)x_s[q];
        float dot = 0.f, na = 0.f;
#pragma unroll
        for (int i = 0; i < 6; ++i) {
            float4 xa = xs4[lane + 32 * i];
            float t;
            t = xa.x * a6[i].x; dot = fmaf(t, k6[i].x, dot); na = fmaf(t, t, na);
            t = xa.y * a6[i].y; dot = fmaf(t, k6[i].y, dot); na = fmaf(t, t, na);
            t = xa.z * a6[i].z; dot = fmaf(t, k6[i].z, dot); na = fmaf(t, t, na);
            t = xa.w * a6[i].w; dot = fmaf(t, k6[i].w, dot); na = fmaf(t, t, na);
        }
#pragma unroll
        for (int off = 16; off; off >>= 1) {
            dot += __shfl_xor_sync(0xFFFFFFFFu, dot, off);
            na  += __shfl_xor_sync(0xFFFFFFFFu, na,  off);
        }
        if (lane == 0)
            sc[q][w] = dot / (fmaxf(sqrtf(na), EPSV) * nKc);
    }
    __syncthreads();

    if (tid < QPB && q0 + tid < BQ) {
        float s[FEND];
#pragma unroll
        for (int k = 0; k < FEND; ++k) s[k] = sc[tid][k];
        float tv[TOPKN]; int ti[TOPKN];
#pragma unroll
        for (int j = 0; j < TOPKN; ++j) {
            int bi = 0; float bv = -__int_as_float(0x7F800000); // -inf
#pragma unroll
            for (int k = 0; k < FEND; ++k)
                if (s[k] > bv) { bv = s[k]; bi = k; }
            tv[j] = bv; ti[j] = bi;
            s[bi] = -__int_as_float(0x7F800000);
        }
        float m = tv[0], sum = 0.f;
        float e[TOPKN];
#pragma unroll
        for (int j = 0; j < TOPKN; ++j) { e[j] = __expf(tv[j] - m); sum += e[j]; }
        float inv = 1.f / sum;
        float g[FEND];
#pragma unroll
        for (int k = 0; k < FEND; ++k) g[k] = 0.f;
#pragma unroll
        for (int j = 0; j < TOPKN; ++j) g[ti[j]] = e[j] * inv;
        // transposed write: gate for (k, q) at g_gateT[k*QMAX + q]
        const int q = q0 + tid;
#pragma unroll
        for (int k = 0; k < FEND; ++k) g_gateT[k * QMAX + q] = g[k];
    }
}

// ---------------------------------------------------------------------------
// Kernel 2: dense K=20 mini-GEMM, 16 queries per warp, COALESCED staging.
// Grid: (P_FEAT/DC, 8, BQ/QB2). Block: 256 threads (8 warps).
// Block tile: 128 queries x 128 d. Warp w owns queries [w*16, w*16+16);
// lane owns 4 d-cols. Per warp-k: 1 p LDS.128 (4 wf) + 4 gate LDS.128
// (uniform broadcast, 4 wf) + 4 pack2 + 32 fma2.
// ---------------------------------------------------------------------------
__global__ __launch_bounds__(K2_THREADS, 2)
void expand_kernel(const float* __restrict__ p,
                   float* __restrict__ out,
                   int BQ) {
    __shared__ float ps_s[FEND * DC];    // [k][128]  10 KB
    __shared__ float gt_s[FEND * QB2];   // [k][128]  10 KB

    const int d0  = blockIdx.x * DC;
    const int l   = blockIdx.y;
    const int q0  = blockIdx.z * QB2;
    const int tid = threadIdx.x;

    // stage p tile: rows k, columns d0..d0+127 of plane (k, l)
    for (int i = tid; i < FEND * (DC / 4); i += K2_THREADS) {
        int k = i / (DC / 4);
        int c = i % (DC / 4);
        ((float4*)ps_s)[i] =
            *(const float4*)(p + ((size_t)(k * E_P_LEN + l)) * P_FEAT + d0 + c * 4);
    }
    // stage gate tile from TRANSPOSED table: linear float4 copy per k-row
    for (int i = tid; i < FEND * (QB2 / 4); i += K2_THREADS) {
        int k = i / (QB2 / 4);
        int c = i % (QB2 / 4);
        int qq = q0 + c * 4;
        float4 v;
        if (qq + 3 < BQ) {
            v = *(const float4*)(g_gateT + (size_t)k * QMAX + qq);
        } else {
            v.x = (qq + 0 < BQ) ? g_gateT[(size_t)k * QMAX + qq + 0] : 0.f;
            v.y = (qq + 1 < BQ) ? g_gateT[(size_t)k * QMAX + qq + 1] : 0.f;
            v.z = (qq + 2 < BQ) ? g_gateT[(size_t)k * QMAX + qq + 2] : 0.f;
            v.w = (qq + 3 < BQ) ? g_gateT[(size_t)k * QMAX + qq + 3] : 0.f;
        }
        ((float4*)gt_s)[i] = v;
    }
    __syncthreads();

    const int lane = tid & 31;    // d position within chunk (x4)
    const int w    = tid >> 5;    // query group of 16

    unsigned long long acc[8][4];
#pragma unroll
    for (int a = 0; a < 8; ++a)
#pragma unroll
        for (int b = 0; b < 4; ++b) acc[a][b] = 0ull;

#pragma unroll 4
    for (int k = 0; k < FEND; ++k) {
        float4 pv = ((const float4*)ps_s)[k * (DC / 4) + lane];
        unsigned long long pp[4];
        pp[0] = pack2(pv.x);
        pp[1] = pack2(pv.y);
        pp[2] = pack2(pv.z);
        pp[3] = pack2(pv.w);
        // 16 gates = 8 query-pairs, uniform per warp
        const ulonglong2* gp = (const ulonglong2*)(gt_s + k * QB2 + w * 16);
        ulonglong2 ga = gp[0];   // pairs 0,1
        ulonglong2 gb = gp[1];   // pairs 2,3
        ulonglong2 gc = gp[2];   // pairs 4,5
        ulonglong2 gd = gp[3];   // pairs 6,7
        unsigned long long gv[8] = { ga.x, ga.y, gb.x, gb.y,
                                     gc.x, gc.y, gd.x, gd.y };
#pragma unroll
        for (int qp = 0; qp < 8; ++qp) {
            fma2(acc[qp][0], gv[qp], pp[0]);
            fma2(acc[qp][1], gv[qp], pp[1]);
            fma2(acc[qp][2], gv[qp], pp[2]);
            fma2(acc[qp][3], gv[qp], pp[3]);
        }
    }

    // writeout: Ek = rows [0, BQ*4), Ev = rows [BQ*4, BQ*8)
    const size_t base = (l < 4) ? 0 : (size_t)BQ * 4;
    const int lrow = l & 3;
    const int dcol = d0 + lane * 4;
#pragma unroll
    for (int qp = 0; qp < 8; ++qp) {
        float2 u0 = unpack2(acc[qp][0]);
        float2 u1 = unpack2(acc[qp][1]);
        float2 u2 = unpack2(acc[qp][2]);
        float2 u3 = unpack2(acc[qp][3]);
        int q = q0 + w * 16 + qp * 2;
        float4 o0 = make_float4(u0.x, u1.x, u2.x, u3.x);
        float4 o1 = make_float4(u0.y, u1.y, u2.y, u3.y);
        if (q < BQ)
            *(float4*)(out + (base + (size_t)q * 4 + lrow) * P_FEAT + dcol) = o0;
        if (q + 1 < BQ)
            *(float4*)(out + (base + (size_t)(q + 1) * 4 + lrow) * P_FEAT + dcol) = o1;
    }
}

// ---------------------------------------------------------------------------
// Launch
// ---------------------------------------------------------------------------
extern "C" void kernel_launch(void* const* d_in, const int* in_sizes, int n_in,
                              void* d_out, int out_size) {
    // Inputs (metadata order): x_querry, l, x_block, K, A, p.
    int iK, iA, ip;
    if (n_in >= 6 && in_sizes[1] == 1) { iK = 3; iA = 4; ip = 5; }
    else                               { iK = 2; iA = 3; ip = 4; }

    const float* x = (const float*)d_in[0];
    const float* K = (const float*)d_in[iK];
    const float* A = (const float*)d_in[iA];
    const float* p = (const float*)d_in[ip];
    float*     out = (float*)d_out;

    const int BQ = in_sizes[0] / KEY_D;   // 1024 for (4, 256)

    scores_gate_kernel<<<(BQ + QPB - 1) / QPB, K1_THREADS>>>(x, K, A, BQ);

    dim3 grid(P_FEAT / DC, E_P_LEN, (BQ + QB2 - 1) / QB2);
    expand_kernel<<<grid, K2_THREADS>>>(p, out, BQ);
}